// round 16
// baseline (speedup 1.0000x reference)
#include <cuda_runtime.h>
#include <stdint.h>

#define COLA 528                 // A row stride (bytes)
#define COLB 544                 // B col stride (bytes)
#define ASZ (128 * COLA)         // 67584
#define BSZ (64 * COLB)          // 34816

// SMEM: sA0 | sA1 | B1 | B2 | bb0 | bb1 | corr
#define SB1_OFF  (2 * ASZ)               // 135168
#define SB2_OFF  (2 * ASZ + BSZ)         // 169984
#define BB0_OFF  (2 * ASZ + 2 * BSZ)     // 204800
#define BB1_OFF  (BB0_OFF + 544)         // 205344
#define CORR_OFF (BB1_OFF + 544)         // 205888
#define SMEM_DYN (CORR_OFF + 256)        // 206144

static __device__ __align__(16) signed char g_Wd1[BSZ];
static __device__ __align__(16) signed char g_Wd2[BSZ];
static __device__ float g_corr[64];
static __device__ float g_sc;
static __device__ int   g_stride;

// ---------------------------------------------------------------------------
__device__ __forceinline__ void imma(int* c, uint32_t a0, uint32_t a1,
                                     uint32_t a2, uint32_t a3,
                                     uint32_t b0, uint32_t b1) {
    asm volatile(
        "mma.sync.aligned.m16n8k32.row.col.s32.s8.s8.s32 "
        "{%0,%1,%2,%3}, {%4,%5,%6,%7}, {%8,%9}, {%0,%1,%2,%3};"
        : "+r"(c[0]), "+r"(c[1]), "+r"(c[2]), "+r"(c[3])
        : "r"(a0), "r"(a1), "r"(a2), "r"(a3), "r"(b0), "r"(b1));
}

#define BAR_SYNC512(id)   asm volatile("bar.sync %0, 512;"   :: "r"(id) : "memory")
#define BAR_ARRIVE512(id) asm volatile("bar.arrive %0, 512;" :: "r"(id) : "memory")
#define BAR_SUP()         asm volatile("bar.sync 5, 256;"    ::: "memory")

// ---------------------------------------------------------------------------
// Prep: two-digit s8 quantization of W in MMA fragment order + column sums
// + input-width detection. (Known-good since R6.)
// ---------------------------------------------------------------------------
static __global__ void bf_prep(const float* __restrict__ W,
                               const uint32_t* __restrict__ xw)
{
    __shared__ float red[512];
    int o = blockIdx.x, k = threadIdx.x;

    if (o == 0 && k == 0) {
        uint32_t acc = 0;
        for (int j = 1; j < 256; j += 2) acc |= xw[j];
        g_stride = (acc == 0u) ? 2 : 1;
    }

    float mx = 0.f;
    for (int i = k; i < 496 * 64; i += 512) mx = fmaxf(mx, fabsf(W[i]));
    red[k] = mx;
    __syncthreads();
    for (int d = 256; d; d >>= 1) {
        if (k < d) red[k] = fmaxf(red[k], red[k + d]);
        __syncthreads();
    }
    float maxabs = fmaxf(red[0], 1e-30f);
    __syncthreads();

    float s1 = maxabs * (1.0f / 127.0f), inv1 = 127.0f / maxabs;
    float inv2 = 128.0f / s1;

    float w = (k < 496) ? W[k * 64 + o] : 0.f;
    int d1 = __float2int_rn(w * inv1);
    d1 = max(-127, min(127, d1));
    float r = w - s1 * (float)d1;
    int d2 = __float2int_rn(r * inv2);          // in [-64, 64]

    int ks = k >> 5, wrd = (k >> 2) & 7, tig = wrd & 3, hf = wrd >> 2, by = k & 3;
    int addr = o * COLB + ks * 32 + tig * 8 + hf * 4 + by;
    g_Wd1[addr] = (signed char)d1;
    g_Wd2[addr] = (signed char)d2;

    red[k] = w;
    __syncthreads();
    for (int d = 256; d; d >>= 1) {
        if (k < d) red[k] += red[k + d];
        __syncthreads();
    }
    if (k == 0) {
        g_corr[o] = red[0] * (1.0f / 255.0f);
        if (o == 0) g_sc = (2.0f / 255.0f) * s1 * (1.0f / 128.0f);
    }
}

// ---------------------------------------------------------------------------
__device__ __forceinline__ void buildA(const uint32_t* __restrict__ bw, char* rowp,
                                       int q, int g4, uint32_t sel0, uint32_t sel1,
                                       uint32_t M1, uint32_t M2, int s)
{
    #pragma unroll
    for (int m = 0; m < 8; m++) {
        int wbase = q * 32 + m * 4;
        uint32_t A0 = bw[wbase + g4];
        uint32_t acc[4];
        #pragma unroll
        for (int j = 0; j < 4; j++) {
            uint32_t B0 = bw[wbase + g4 + j + 1];
            uint32_t X = __byte_perm(A0, B0, sel0);
            uint32_t Y = __byte_perm(A0, B0, sel1);
            acc[j] = (((X << s) & M1) | ((Y >> (8 - s)) & M2)) ^ 0x80808080u;
            A0 = B0;
        }
        *(uint4*)(rowp + m * 16) = make_uint4(acc[0], acc[1], acc[2], acc[3]);
    }
}

// fetch 2 input bytes (elements 2ts, 2ts+1 of tile n) packed into one reg
__device__ __forceinline__ uint32_t fetch2(const uint32_t* __restrict__ xw,
                                           int n, int ts, int stride) {
    const uint32_t* p = xw + ((size_t)n * 512 + 2 * ts) * (size_t)stride;
    return (p[0] & 255u) | ((p[stride] & 255u) << 8);
}

// ---------------------------------------------------------------------------
// Warp-specialized persistent kernel: grid 148 x 512, 1 CTA/SM.
// Warps 0-7: MMA consumers. Warps 8-15: producers (bytes + A build).
// KEY CHANGE vs R14: consumers arrive free[p] IMMEDIATELY after the MMA loop
// (A is dead once read), then do the epilogue — producers rebuild A[p]
// concurrently with the consumer epilogue, hiding both build and epilogue.
// ---------------------------------------------------------------------------
static __global__ void __launch_bounds__(512, 1)
bf_main(const uint32_t* __restrict__ xw, float* __restrict__ out)
{
    extern __shared__ __align__(16) char sm[];
    char* sA0 = sm;
    char* sA1 = sm + ASZ;
    char* sB1 = sm + SB1_OFF;
    char* sB2 = sm + SB2_OFF;
    uint32_t* bb0 = (uint32_t*)(sm + BB0_OFF);
    uint32_t* bb1 = (uint32_t*)(sm + BB1_OFF);
    float* scorr  = (float*)(sm + CORR_OFF);

    const int t = threadIdx.x, lane = t & 31, wid = t >> 5;
    const int stride = g_stride;
    const float sc = g_sc;
    const int n0 = blockIdx.x;

    // ---- prologue: copy B digits + corr, zero byte pads ----
    {
        const uint4* w1 = (const uint4*)g_Wd1;
        const uint4* w2 = (const uint4*)g_Wd2;
        uint4* p1 = (uint4*)sB1;
        uint4* p2 = (uint4*)sB2;
        for (int i = t; i < BSZ / 16; i += 512) { p1[i] = w1[i]; p2[i] = w2[i]; }
        if (t < 64) scorr[t] = g_corr[t];
        if (t < 8)  { bb0[128 + t] = 0u; bb1[128 + t] = 0u; }
    }
    __syncthreads();

    if (wid < 8) {
        // ================= MMA CONSUMER WARPS =================
        const int rb = wid * 16;
        const int gid = lane >> 2, tig = lane & 3;
        const int aOff = rb * COLA + gid * COLA + 4 * tig;
        const int row0 = rb + gid;
        int bCol[8];
        #pragma unroll
        for (int nt = 0; nt < 8; nt++) bCol[nt] = (nt * 8 + gid) * COLB + tig * 8;
        float corr0[8], corr1[8];
        #pragma unroll
        for (int nt = 0; nt < 8; nt++) {
            int col = nt * 8 + 2 * tig;
            corr0[nt] = scorr[col];
            corr1[nt] = scorr[col + 1];
        }

        int i = 0;
        for (int n = n0; n < 2048; n += 148, i++) {
            const int p = i & 1;
            BAR_SYNC512(1 + p);                       // wait full[p]
            const char* aR = (p ? sA1 : sA0) + aOff;

            int c1[32], c2[32];
            #pragma unroll
            for (int j = 0; j < 32; j++) { c1[j] = 0; c2[j] = 0; }

            #pragma unroll
            for (int ks = 0; ks < 16; ks++) {
                int k0 = ks * 32;
                uint32_t a0 = *(const uint32_t*)(aR + k0);
                uint32_t a2 = *(const uint32_t*)(aR + k0 + 16);
                uint32_t a1 = *(const uint32_t*)(aR + 8 * COLA + k0);
                uint32_t a3 = *(const uint32_t*)(aR + 8 * COLA + k0 + 16);
                #pragma unroll
                for (int nt = 0; nt < 8; nt++) {
                    uint2 b = *(const uint2*)(sB1 + bCol[nt] + k0);
                    imma(c1 + 4 * nt, a0, a1, a2, a3, b.x, b.y);
                    uint2 e = *(const uint2*)(sB2 + bCol[nt] + k0);
                    imma(c2 + 4 * nt, a0, a1, a2, a3, e.x, e.y);
                }
            }

            BAR_ARRIVE512(3 + p);                     // A[p] dead -> free NOW

            // epilogue (overlapped with producers rebuilding A[p])
            {
                float* po = out + (size_t)n * 8192;
                #pragma unroll
                for (int nt = 0; nt < 8; nt++) {
                    int col = nt * 8 + 2 * tig;
                    float2 v0, v1;
                    v0.x = fmaf(sc, (float)((c1[4*nt+0] << 7) + c2[4*nt+0]), corr0[nt]);
                    v0.y = fmaf(sc, (float)((c1[4*nt+1] << 7) + c2[4*nt+1]), corr1[nt]);
                    v1.x = fmaf(sc, (float)((c1[4*nt+2] << 7) + c2[4*nt+2]), corr0[nt]);
                    v1.y = fmaf(sc, (float)((c1[4*nt+3] << 7) + c2[4*nt+3]), corr1[nt]);
                    __stcs((float2*)(po + row0 * 64 + col), v0);
                    __stcs((float2*)(po + (row0 + 8) * 64 + col), v1);
                }
            }
        }
    } else {
        // ================= SUPPORT PRODUCER WARPS =================
        const int sw = wid - 8;
        const int ts = sw * 32 + lane;                // 0..255: bytes 2ts, 2ts+1

        int qv[2], g4v[2], sv[2], rowOff[2];
        uint32_t sel0v[2], sel1v[2], M1v[2], M2v[2];
        #pragma unroll
        for (int j = 0; j < 2; j++) {
            int task = lane + 32 * j;                 // 0..63
            int rl = task >> 2, q = task & 3;
            int r = sw * 16 + rl;
            int g = r >> 3, s = r & 7;
            qv[j] = q;
            g4v[j] = g >> 2;
            sv[j] = s;
            sel0v[j] = 0x3210u + 0x1111u * (uint32_t)(g & 3);
            sel1v[j] = sel0v[j] + 0x1111u;
            M1v[j] = 0x01010101u * ((0xFFu << s) & 0xFFu);
            M2v[j] = 0x01010101u * (0xFFu >> (8 - s));
            rowOff[j] = r * COLA + q * 128;
        }

        uint32_t breg = fetch2(xw, n0, ts, stride);   // bytes(n0)

        int i = 0;
        for (int n = n0; n < 2048; n += 148, i++) {
            const int p = i & 1;
            uint32_t* bb = p ? bb1 : bb0;

            ((unsigned short*)bb)[ts] = (unsigned short)breg;
            {
                int nb = n + 148; if (nb > 2047) nb = 2047;
                breg = fetch2(xw, nb, ts, stride);
            }
            BAR_SUP();                                 // bb[p] committed
            if (i >= 2) BAR_SYNC512(3 + p);            // wait free[p]

            char* base = p ? sA1 : sA0;
            buildA(bb, base + rowOff[0], qv[0], g4v[0], sel0v[0], sel1v[0],
                   M1v[0], M2v[0], sv[0]);
            buildA(bb, base + rowOff[1], qv[1], g4v[1], sel0v[1], sel1v[1],
                   M1v[1], M2v[1], sv[1]);
            BAR_ARRIVE512(1 + p);                      // signal full[p]
        }
    }
}

// ---------------------------------------------------------------------------
extern "C" void kernel_launch(void* const* d_in, const int* in_sizes, int n_in,
                              void* d_out, int out_size)
{
    const uint32_t* xw  = (const uint32_t*)d_in[0];
    const float*    W   = (const float*)d_in[1];
    float*          out = (float*)d_out;

    cudaFuncSetAttribute(bf_main, cudaFuncAttributeMaxDynamicSharedMemorySize, SMEM_DYN);
    bf_prep<<<64, 512>>>(W, xw);
    bf_main<<<148, 512, SMEM_DYN>>>(xw, out);
}